// round 14
// baseline (speedup 1.0000x reference)
#include <cuda_runtime.h>
#include <cuda_fp16.h>
#include <math.h>
#include <stdint.h>
#include <string.h>

// Problem constants
#define BB 32
#define TT 256
#define DD 1024
#define HH 8
#define DH 128
#define HID 256
#define MTOT (BB*TT)          // 8192
#define XF 2560

// ------------------------- scratch (static device memory) -------------------
__device__ float  g_h  [MTOT*DD];        // fp32 residual stream
__device__ __half g_hh [MTOT*DD];        // fp16 copy of h
__device__ __half g_xh [MTOT*XF];        // fp16 copy of x
__device__ __half g_qkv[MTOT*3072];      // fp16 qkv
__device__ __half g_ao [MTOT*DD];        // fp16 attention out
__device__ float  g_gx [MTOT*1536];      // fp32 GRU input projections
__device__ float  g_hstate[2*2*BB*HID];  // [dir][buf][batch][unit]
__device__ unsigned g_bar[16];
__device__ int g_len[BB];
__device__ float g_bias[2*3072 + 1536];

// fp16 weights, [N][K] layout
#define OFF_TRAN 0
#define OFF_QKV(l) (786432 + (size_t)(l)*3145728)
#define OFF_O(l)   (7077888 + (size_t)(l)*1048576)
#define OFF_IH     9175040
#define WH_ELEMS   10747904
__device__ __half g_Wh[WH_ELEMS];

// ------------------------- helpers ------------------------------------------
__device__ __forceinline__ uint32_t smem_u32(const void* p) {
    uint32_t a;
    asm("{ .reg .u64 t; cvta.to.shared.u64 t, %1; cvt.u32.u64 %0, t; }" : "=r"(a) : "l"(p));
    return a;
}
__device__ __forceinline__ void ldsm4(uint32_t* r, uint32_t addr) {
    asm volatile("ldmatrix.sync.aligned.m8n8.x4.shared.b16 {%0,%1,%2,%3}, [%4];"
        : "=r"(r[0]), "=r"(r[1]), "=r"(r[2]), "=r"(r[3]) : "r"(addr));
}
__device__ __forceinline__ void mma_fp16(float* c, const uint32_t* a, uint32_t b0, uint32_t b1) {
    asm volatile(
        "mma.sync.aligned.m16n8k16.row.col.f32.f16.f16.f32 "
        "{%0,%1,%2,%3}, {%4,%5,%6,%7}, {%8,%9}, {%0,%1,%2,%3};"
        : "+f"(c[0]), "+f"(c[1]), "+f"(c[2]), "+f"(c[3])
        : "r"(a[0]), "r"(a[1]), "r"(a[2]), "r"(a[3]), "r"(b0), "r"(b1));
}
__device__ __forceinline__ void cp16(uint32_t sdst, const void* gsrc) {
    asm volatile("cp.async.cg.shared.global [%0], [%1], 16;" :: "r"(sdst), "l"(gsrc));
}
#define CP_COMMIT() asm volatile("cp.async.commit_group;" ::: "memory")
#define CP_WAIT1()  asm volatile("cp.async.wait_group 1;" ::: "memory")

__device__ __forceinline__ unsigned ld_acq(const unsigned* p) {
    unsigned v;
    asm volatile("ld.acquire.gpu.global.u32 %0, [%1];" : "=r"(v) : "l"(p) : "memory");
    return v;
}
__device__ __forceinline__ void red_release(unsigned* p, unsigned v) {
    asm volatile("red.release.gpu.global.add.u32 [%0], %1;" :: "l"(p), "r"(v) : "memory");
}

// packed f32x2 fma (sm_100+ base ISA)
__device__ __forceinline__ void fma2(unsigned long long& c, unsigned long long a, unsigned long long b) {
    asm volatile("fma.rn.f32x2 %0, %1, %2, %0;" : "+l"(c) : "l"(a), "l"(b));
}
__device__ __forceinline__ float pairsum(unsigned long long v) {
    float2 f; memcpy(&f, &v, 8); return f.x + f.y;
}
__device__ __forceinline__ float4 ldcg4(const float* p) {
    float4 v;
    asm volatile("ld.global.cg.v4.f32 {%0,%1,%2,%3}, [%4];"
        : "=f"(v.x), "=f"(v.y), "=f"(v.z), "=f"(v.w) : "l"(p));
    return v;
}

// ------------------------- fused prep kernel --------------------------------
#define PB0 32                       // prep:      [0, 32)
#define PB1 (PB0 + 30)               // pack_bias: [32, 62)
#define PB2 (PB1 + 768)              // tran:      [62, 830)
#define PB3 (PB2 + 8192)             // qkvo:      [830, 9022)
#define PB4 (PB3 + 768)              // ih conv:   [9022, 9790)
#define PB5 (PB4 + 10240)            // xconv:     [9790, 20030)
__global__ __launch_bounds__(256) void wprep(
    const int* __restrict__ mask,
    const float* __restrict__ bq, const float* __restrict__ bk, const float* __restrict__ bv,
    const float* __restrict__ bihf, const float* __restrict__ bihb,
    const float* __restrict__ W_tran,
    const float* __restrict__ Wq, const float* __restrict__ Wk,
    const float* __restrict__ Wv, const float* __restrict__ Wo,
    const float* __restrict__ Wihf, const float* __restrict__ Wihb,
    const float* __restrict__ x,
    __half* __restrict__ wh, __half* __restrict__ xh)
{
    __shared__ __align__(16) char shbuf[32*33*4];
    int b = blockIdx.x;
    int tid = threadIdx.x;

    if (b < PB0) {
        int* red = (int*)shbuf;
        red[tid] = mask[b*TT + tid];
        __syncthreads();
        for (int st = 128; st > 0; st >>= 1) {
            if (tid < st) red[tid] += red[tid + st];
            __syncthreads();
        }
        if (tid == 0) g_len[b] = red[0];
        if (b == 0 && tid < 16) g_bar[tid] = 0u;
    } else if (b < PB1) {
        int idx = (b - PB0) * 256 + tid;
        if (idx < 6144) {
            int l = idx / 3072, j = idx % 3072;
            float v;
            if (j < 1024)      v = bq[l*1024 + j];
            else if (j < 2048) v = bk[l*1024 + j - 1024];
            else               v = bv[l*1024 + j - 2048];
            g_bias[idx] = v;
        } else {
            int j = idx - 6144;
            g_bias[idx] = (j < 768) ? bihf[j] : bihb[j - 768];
        }
    } else if (b < PB3) {
        const float* W; __half* out; int K, N, bx, by;
        if (b < PB2) {
            int i2 = b - PB1;
            W = W_tran; out = wh + OFF_TRAN; K = 1536; N = 512;
            bx = i2 & 15; by = i2 >> 4;
        } else {
            int i2 = b - PB2;
            int unit = i2 >> 10, w = i2 & 1023;
            int l = unit >> 2, j = unit & 3;
            const float* src = (j == 0) ? Wq : (j == 1) ? Wk : (j == 2) ? Wv : Wo;
            W = src + (size_t)l * DD * DD;
            out = (j < 3) ? (wh + OFF_QKV(l) + (size_t)j * 1048576) : (wh + OFF_O(l));
            K = DD; N = DD;
            bx = w & 31; by = w >> 5;
        }
        float (*ts)[33] = (float(*)[33])shbuf;
        int tx = tid & 31, ty = tid >> 5;
        int n0 = bx * 32, k0 = by * 32;
#pragma unroll
        for (int i = 0; i < 4; i++)
            ts[ty + i*8][tx] = W[(size_t)(k0 + ty + i*8) * N + n0 + tx];
        __syncthreads();
#pragma unroll
        for (int i = 0; i < 4; i++) {
            int n = n0 + ty + i*8, k = k0 + tx;
            out[(size_t)n * K + k] = __float2half_rn(ts[tx][ty + i*8]);
        }
    } else if (b < PB4) {
        int i2 = b - PB3;
        const float* src = (i2 < 384) ? Wihf : Wihb;
        __half* dst = wh + OFF_IH + ((i2 < 384) ? 0 : 786432);
        int base = ((i2 < 384) ? i2 : i2 - 384) * 256 + tid;
        float4 f0 = ((const float4*)src)[base*2];
        float4 f1 = ((const float4*)src)[base*2 + 1];
        __half2 h0 = __floats2half2_rn(f0.x, f0.y);
        __half2 h1 = __floats2half2_rn(f0.z, f0.w);
        __half2 h2 = __floats2half2_rn(f1.x, f1.y);
        __half2 h3 = __floats2half2_rn(f1.z, f1.w);
        uint4 u;
        u.x = *reinterpret_cast<uint32_t*>(&h0);
        u.y = *reinterpret_cast<uint32_t*>(&h1);
        u.z = *reinterpret_cast<uint32_t*>(&h2);
        u.w = *reinterpret_cast<uint32_t*>(&h3);
        ((uint4*)dst)[base] = u;
    } else {
        int base = (b - PB4) * 256 + tid;
        float4 f0 = ((const float4*)x)[base*2];
        float4 f1 = ((const float4*)x)[base*2 + 1];
        __half2 h0 = __floats2half2_rn(f0.x, f0.y);
        __half2 h1 = __floats2half2_rn(f0.z, f0.w);
        __half2 h2 = __floats2half2_rn(f1.x, f1.y);
        __half2 h3 = __floats2half2_rn(f1.z, f1.w);
        uint4 u;
        u.x = *reinterpret_cast<uint32_t*>(&h0);
        u.y = *reinterpret_cast<uint32_t*>(&h1);
        u.z = *reinterpret_cast<uint32_t*>(&h2);
        u.w = *reinterpret_cast<uint32_t*>(&h3);
        ((uint4*)xh)[base] = u;
    }
}

// sentinel: positions the ncu profiling window
__global__ void sentinel_k() {}

// ------------------------- HMMA fp16 GEMM (R12 config) ----------------------
// C = A[M,K](fp16) * B[N,K](fp16)^T + bias (+R fp32)
// grid (N/128, M/128), 256 threads (8 warps: 4m x 2n), K % 64 == 0, K/64 >= 2.
#define TILE144 18432                 // 128 rows * 144B pitch
#define STAGE_B (2*TILE144)           // 36864
#define GEMM_SMEM (2*STAGE_B)         // 73728

template<bool RESID, bool WF, bool WH>
__global__ __launch_bounds__(256) void gemm_h(
    const __half* __restrict__ A, int lda,
    const __half* __restrict__ B,
    const float* __restrict__ bias,
    const float* __restrict__ R, int ldr,
    float* __restrict__ Cf, __half* __restrict__ Ch,
    int N, int K)
{
    extern __shared__ char smem[];
    uint32_t sb = smem_u32(smem);
    int tid = threadIdx.x;
    int lane = tid & 31;
    int wid = tid >> 5;
    int warp_m = wid & 3;
    int warp_n = wid >> 2;
    int bn = blockIdx.x * 128, bm = blockIdx.y * 128;

    float acc[2][8][4];
#pragma unroll
    for (int a = 0; a < 2; a++)
#pragma unroll
        for (int b = 0; b < 8; b++)
#pragma unroll
            for (int c = 0; c < 4; c++) acc[a][b][c] = 0.f;

#define ISSUE(k0idx, stg)                                                      \
    {                                                                          \
        int k0 = (k0idx) * 64;                                                 \
        uint32_t sa = sb + (stg) * STAGE_B;                                    \
        _Pragma("unroll")                                                      \
        for (int i = 0; i < 4; i++) {                                          \
            int linear = tid + i * 256;                                        \
            int row = linear >> 3, cc = linear & 7;                            \
            cp16(sa + row*144 + cc*16,                                         \
                 A + (size_t)(bm + row) * lda + k0 + cc*8);                    \
            cp16(sa + TILE144 + row*144 + cc*16,                               \
                 B + (size_t)(bn + row) * K + k0 + cc*8);                      \
        }                                                                      \
    }

    const int NC = K / 64;
    ISSUE(0, 0); CP_COMMIT();
    ISSUE(1, 1); CP_COMMIT();

    for (int ch = 0; ch < NC; ch++) {
        CP_WAIT1();
        __syncthreads();

        uint32_t sbase = sb + (ch & 1) * STAGE_B;
#pragma unroll
        for (int ks = 0; ks < 4; ks++) {
            int kofs = ks * 32;   // bytes (16 halfs)
            uint32_t ah[2][4];
#pragma unroll
            for (int mf = 0; mf < 2; mf++) {
                uint32_t row = warp_m * 32 + mf * 16 + (lane & 15);
                uint32_t addr = sbase + row * 144 + kofs + ((lane >> 4) * 16);
                ldsm4(ah[mf], addr);
            }
#pragma unroll
            for (int np = 0; np < 4; np++) {
                uint32_t rown = warp_n * 64 + np * 16 + (lane & 7) + ((lane >> 4) << 3);
                uint32_t addr = sbase + TILE144 + rown * 144 + kofs + (((lane >> 3) & 1) * 16);
                uint32_t b[4];
                ldsm4(b, addr);
#pragma unroll
                for (int mf = 0; mf < 2; mf++) {
                    mma_fp16(acc[mf][np*2],   ah[mf], b[0], b[1]);
                    mma_fp16(acc[mf][np*2+1], ah[mf], b[2], b[3]);
                }
            }
        }

        __syncthreads();
        int nxt = ch + 2;
        if (nxt < NC) ISSUE(nxt, nxt & 1);
        CP_COMMIT();
    }

    // ---- epilogue ----
#pragma unroll
    for (int mf = 0; mf < 2; mf++) {
        int row0 = bm + warp_m * 32 + mf * 16 + (lane >> 2);
        int row1 = row0 + 8;
#pragma unroll
        for (int nf = 0; nf < 8; nf++) {
            int col = bn + warp_n * 64 + nf * 8 + (lane & 3) * 2;
            float2 bs = *(const float2*)(bias + col);
            float* a4 = acc[mf][nf];
            float2 o0 = make_float2(a4[0] + bs.x, a4[1] + bs.y);
            float2 o1 = make_float2(a4[2] + bs.x, a4[3] + bs.y);
            if (RESID) {
                float2 r0 = *(const float2*)(R + (size_t)row0 * ldr + col);
                float2 r1 = *(const float2*)(R + (size_t)row1 * ldr + col);
                o0.x += r0.x; o0.y += r0.y;
                o1.x += r1.x; o1.y += r1.y;
            }
            if (WF) {
                *(float2*)(Cf + (size_t)row0 * N + col) = o0;
                *(float2*)(Cf + (size_t)row1 * N + col) = o1;
            }
            if (WH) {
                *(__half2*)(Ch + (size_t)row0 * N + col) = __floats2half2_rn(o0.x, o0.y);
                *(__half2*)(Ch + (size_t)row1 * N + col) = __floats2half2_rn(o1.x, o1.y);
            }
        }
    }
#undef ISSUE
}

// ------------------------- banded attention (fp16 in/out) -------------------
__global__ __launch_bounds__(256) void band_attn(
    const __half* __restrict__ qkv, __half* __restrict__ o)
{
    int t = blockIdx.x, b = blockIdx.y;
    int hh = threadIdx.x >> 5;
    int lane = threadIdx.x & 31;
    const float scale = 0.088388347648318447f;

    size_t qb = ((size_t)(b*TT + t))*3072 + hh*DH + lane*4;
    float2 q01, q23;
    {
        const __half2* qp = (const __half2*)(qkv + qb);
        q01 = __half22float2(qp[0]);
        q23 = __half22float2(qp[1]);
    }

    float s[7];
    float m = -1e30f;
#pragma unroll
    for (int jj = 0; jj < 7; jj++) {
        int j = t - 3 + jj;
        bool ok = (j >= 0) && (j < TT);
        int jc = j < 0 ? 0 : (j > TT-1 ? TT-1 : j);
        size_t kb = ((size_t)(b*TT + jc))*3072 + 1024 + hh*DH + lane*4;
        const __half2* kp = (const __half2*)(qkv + kb);
        float2 k01 = __half22float2(kp[0]);
        float2 k23 = __half22float2(kp[1]);
        float d = q01.x*k01.x + q01.y*k01.y + q23.x*k23.x + q23.y*k23.y;
        d += __shfl_xor_sync(0xffffffffu, d, 16);
        d += __shfl_xor_sync(0xffffffffu, d, 8);
        d += __shfl_xor_sync(0xffffffffu, d, 4);
        d += __shfl_xor_sync(0xffffffffu, d, 2);
        d += __shfl_xor_sync(0xffffffffu, d, 1);
        d *= scale;
        s[jj] = ok ? d : -1e30f;
        m = fmaxf(m, s[jj]);
    }
    float sum = 0.f;
#pragma unroll
    for (int jj = 0; jj < 7; jj++) { s[jj] = expf(s[jj] - m); sum += s[jj]; }
    float inv = 1.f / sum;

    float4 acc = make_float4(0.f, 0.f, 0.f, 0.f);
#pragma unroll
    for (int jj = 0; jj < 7; jj++) {
        int j = t - 3 + jj;
        int jc = j < 0 ? 0 : (j > TT-1 ? TT-1 : j);
        size_t vb = ((size_t)(b*TT + jc))*3072 + 2048 + hh*DH + lane*4;
        const __half2* vp = (const __half2*)(qkv + vb);
        float2 v01 = __half22float2(vp[0]);
        float2 v23 = __half22float2(vp[1]);
        float p = s[jj] * inv;
        acc.x += p*v01.x; acc.y += p*v01.y; acc.z += p*v23.x; acc.w += p*v23.y;
    }
    size_t ob = ((size_t)(b*TT + t))*DD + hh*DH + lane*4;
    *(__half2*)(o + ob)     = __floats2half2_rn(acc.x, acc.y);
    *(__half2*)(o + ob + 2) = __floats2half2_rn(acc.z, acc.w);
}

// ------------------------- persistent bidirectional GRU ---------------------
// 128 CTAs: dir(2) x unit-group(8, 32 units) x batch-group(8, 4 batches)
// all-thread acquire-poll; h loaded DIRECTLY from L2 inside the fma loop
// (each thread's own acquire orders its loads — no smem staging / extra sync)
__global__ __launch_bounds__(128) void gru_kernel(
    const float* __restrict__ gx,
    const float* __restrict__ Whf, const float* __restrict__ Whb,
    const float* __restrict__ bhf, const float* __restrict__ bhb,
    float* __restrict__ out)
{
    extern __shared__ float sm[];
    float* ws = sm;                   // [3*32][260]

    int cta = blockIdx.x;
    int dir = cta >> 6;
    int ug  = (cta >> 3) & 7;
    int bg  = cta & 7;
    int grp = (dir << 3) | bg;
    int tid = threadIdx.x;
    int u   = tid >> 2;
    int bl  = tid & 3;
    int unit  = ug*32 + u;
    int batch = bg*4 + bl;

    const float* Wh = dir ? Whb : Whf;
    const float* bh = dir ? bhb : bhf;

    for (int idx = tid; idx < 3*32*256; idx += 128) {
        int g   = idx >> 13;
        int rem = idx & 8191;
        int uu  = rem >> 8;
        int kk  = rem & 255;
        ws[(g*32 + uu)*260 + kk] = Wh[((g << 8) + ug*32 + uu)*256 + kk];
    }
    float br  = bh[unit];
    float bz  = bh[256 + unit];
    float bnn = bh[512 + unit];
    int len = g_len[batch];

    __stcg(&g_hstate[((dir*2 + 0)*BB + batch)*HID + unit], 0.f);
    __syncthreads();
    if (tid == 0) red_release(&g_bar[grp], 1u);

    const float* wr = &ws[(0*32 + u)*260];
    const float* wz = &ws[(1*32 + u)*260];
    const float* wn = &ws[(2*32 + u)*260];

    unsigned target = 8u;
    for (int s = 0; s < TT; s++, target += 8u) {
        // gx AND out prefetch: h-independent, issue before the spin
        int tt;
        if (dir == 0) tt = s;
        else { int ti = len - 1 - s; tt = ti < 0 ? 0 : ti; }
        const float* gxp = gx + ((size_t)batch*TT + tt)*1536 + dir*768;
        float gr = gxp[unit];
        float gz = gxp[256 + unit];
        float gn = gxp[512 + unit];

        float* op = nullptr;
        float oprev = 0.f;
        if (s < len) {
            int tout = (dir == 0) ? s : (len - 1 - s);
            op = out + ((size_t)batch*TT + tout)*512 + dir*256 + unit;
            oprev = *op;                  // prefetch old value (x_face contrib)
        }

        // all threads poll (acquire) — orders this thread's h loads
        while (ld_acq(&g_bar[grp]) < target) {}

        // h for this thread's batch, straight from L2
        const float* hrow = &g_hstate[((dir*2 + (s & 1))*BB + batch)*HID];
        float hp = __ldcg(hrow + unit);

        unsigned long long ar0=0, ar1=0, az0=0, az1=0, an0=0, an1=0;
#pragma unroll 8
        for (int kk = 0; kk < 256; kk += 4) {
            float4 h4 = ldcg4(hrow + kk);
            unsigned long long hx, hy;
            { float2 t0 = make_float2(h4.x, h4.y); memcpy(&hx, &t0, 8); }
            { float2 t1 = make_float2(h4.z, h4.w); memcpy(&hy, &t1, 8); }
            ulonglong2 w1 = *(const ulonglong2*)(wr + kk);
            ulonglong2 w2 = *(const ulonglong2*)(wz + kk);
            ulonglong2 w3 = *(const ulonglong2*)(wn + kk);
            fma2(ar0, hx, w1.x); fma2(ar1, hy, w1.y);
            fma2(az0, hx, w2.x); fma2(az1, hy, w2.y);
            fma2(an0, hx, w3.x); fma2(an1, hy, w3.y);
        }
        float ghr = pairsum(ar0) + pairsum(ar1);
        float ghz = pairsum(az0) + pairsum(az1);
        float ghn = pairsum(an0) + pairsum(an1);

        float r = 1.f / (1.f + expf(-(gr + ghr + br)));
        float z = 1.f / (1.f + expf(-(gz + ghz + bz)));
        float n = tanhf(gn + r*(ghn + bnn));
        float hn = (1.f - z)*n + z*hp;

        // critical-path tail: publish h, release, then pure store of out
        __stcg(&g_hstate[((dir*2 + ((s+1) & 1))*BB + batch)*HID + unit], hn);
        __syncthreads();
        if (tid == 0) red_release(&g_bar[grp], 1u);

        if (op) *op = oprev + hn;
    }
}

// ------------------------- launch ------------------------------------------
extern "C" void kernel_launch(void* const* d_in, const int* in_sizes, int n_in,
                              void* d_out, int out_size)
{
    const float* x      = (const float*)d_in[0];
    const int*   mask   = (const int*)  d_in[1];
    const float* W_tran = (const float*)d_in[2];
    const float* b_tran = (const float*)d_in[3];
    const float* Wq     = (const float*)d_in[4];
    const float* bq     = (const float*)d_in[5];
    const float* Wk     = (const float*)d_in[6];
    const float* bk     = (const float*)d_in[7];
    const float* Wv     = (const float*)d_in[8];
    const float* bv     = (const float*)d_in[9];
    const float* Wo     = (const float*)d_in[10];
    const float* bo     = (const float*)d_in[11];
    const float* Wihf   = (const float*)d_in[12];
    const float* Whhf   = (const float*)d_in[13];
    const float* bihf   = (const float*)d_in[14];
    const float* bhhf   = (const float*)d_in[15];
    const float* Wihb   = (const float*)d_in[16];
    const float* Whhb   = (const float*)d_in[17];
    const float* bihb   = (const float*)d_in[18];
    const float* bhhb   = (const float*)d_in[19];
    float* out = (float*)d_out;

    float *hbuf, *gxb, *biasbuf;
    __half *wh, *xh, *hh, *qkvh, *aoh;
    cudaGetSymbolAddress((void**)&hbuf,  g_h);
    cudaGetSymbolAddress((void**)&hh,    g_hh);
    cudaGetSymbolAddress((void**)&xh,    g_xh);
    cudaGetSymbolAddress((void**)&qkvh,  g_qkv);
    cudaGetSymbolAddress((void**)&aoh,   g_ao);
    cudaGetSymbolAddress((void**)&gxb,   g_gx);
    cudaGetSymbolAddress((void**)&wh,    g_Wh);
    cudaGetSymbolAddress((void**)&biasbuf, g_bias);

    const int smem_gru = (3*32*260) * 4;  // 99,840 B
    cudaFuncSetAttribute(gru_kernel, cudaFuncAttributeMaxDynamicSharedMemorySize, 112*1024);
    cudaFuncSetAttribute(gemm_h<false,true,false>,  cudaFuncAttributeMaxDynamicSharedMemorySize, GEMM_SMEM);
    cudaFuncSetAttribute(gemm_h<false,false,true>,  cudaFuncAttributeMaxDynamicSharedMemorySize, GEMM_SMEM);
    cudaFuncSetAttribute(gemm_h<true,true,true>,    cudaFuncAttributeMaxDynamicSharedMemorySize, GEMM_SMEM);

    // one fused prep launch
    wprep<<<PB5, 256>>>(mask, bq, bk, bv, bihf, bihb,
                        W_tran, Wq, Wk, Wv, Wo, Wihf, Wihb, x, wh, xh);

    // x_face -> out (fp32)
    gemm_h<false,true,false><<<dim3(4, 64), 256, GEMM_SMEM>>>(
        xh + 1024, XF, wh + OFF_TRAN, b_tran, nullptr, 0, out, nullptr, 512, 1536);

    // sentinel: aligns the ncu window onto a QKV GEMM
    sentinel_k<<<1, 32>>>();

    for (int l = 0; l < 2; l++) {
        const __half* Ain = (l == 0) ? xh : hh;
        int lda = (l == 0) ? XF : DD;

        // fused QKV: N = 3072, fp16 out
        gemm_h<false,false,true><<<dim3(24, 64), 256, GEMM_SMEM>>>(
            Ain, lda, wh + OFF_QKV(l), biasbuf + l*3072, nullptr, 0,
            nullptr, qkvh, 3072, DD);

        band_attn<<<dim3(TT, BB), 256>>>(qkvh, aoh);

        // O proj + residual: fp32 h and fp16 hh outputs
        const float* Rres = (l == 0) ? x : hbuf;
        int ldr = (l == 0) ? XF : DD;
        gemm_h<true,true,true><<<dim3(8, 64), 256, GEMM_SMEM>>>(
            aoh, DD, wh + OFF_O(l), bo + (size_t)l*DD, Rres, ldr,
            hbuf, hh, DD, DD);
    }

    // fused GRU input projections: N = 1536 (f | b), fp32 out
    gemm_h<false,true,false><<<dim3(12, 64), 256, GEMM_SMEM>>>(
        hh, DD, wh + OFF_IH, biasbuf + 6144, nullptr, 0, gxb, nullptr, 1536, DD);

    // persistent bidirectional GRU, writes out = x_face + ys
    gru_kernel<<<128, 128, smem_gru>>>(gxb, Whhf, Whhb, bhhf, bhhb, out);
}

// round 15
// speedup vs baseline: 1.6545x; 1.6545x over previous
#include <cuda_runtime.h>
#include <cuda_fp16.h>
#include <math.h>
#include <stdint.h>
#include <string.h>

// Problem constants
#define BB 32
#define TT 256
#define DD 1024
#define HH 8
#define DH 128
#define HID 256
#define MTOT (BB*TT)          // 8192
#define XF 2560

// ------------------------- scratch (static device memory) -------------------
__device__ float  g_h  [MTOT*DD];        // fp32 residual stream
__device__ __half g_hh [MTOT*DD];        // fp16 copy of h
__device__ __half g_xh [MTOT*XF];        // fp16 copy of x
__device__ __half g_qkv[MTOT*3072];      // fp16 qkv
__device__ __half g_ao [MTOT*DD];        // fp16 attention out
__device__ float  g_gx [MTOT*1536];      // fp32 GRU input projections
__device__ float  g_hstate[2*2*BB*HID];  // [dir][buf][batch][unit]
__device__ unsigned g_bar[16];
__device__ int g_len[BB];
__device__ float g_bias[2*3072 + 1536];

// fp16 weights, [N][K] layout
#define OFF_TRAN 0
#define OFF_QKV(l) (786432 + (size_t)(l)*3145728)
#define OFF_O(l)   (7077888 + (size_t)(l)*1048576)
#define OFF_IH     9175040
#define WH_ELEMS   10747904
__device__ __half g_Wh[WH_ELEMS];

// ------------------------- helpers ------------------------------------------
__device__ __forceinline__ uint32_t smem_u32(const void* p) {
    uint32_t a;
    asm("{ .reg .u64 t; cvta.to.shared.u64 t, %1; cvt.u32.u64 %0, t; }" : "=r"(a) : "l"(p));
    return a;
}
__device__ __forceinline__ void ldsm4(uint32_t* r, uint32_t addr) {
    asm volatile("ldmatrix.sync.aligned.m8n8.x4.shared.b16 {%0,%1,%2,%3}, [%4];"
        : "=r"(r[0]), "=r"(r[1]), "=r"(r[2]), "=r"(r[3]) : "r"(addr));
}
__device__ __forceinline__ void mma_fp16(float* c, const uint32_t* a, uint32_t b0, uint32_t b1) {
    asm volatile(
        "mma.sync.aligned.m16n8k16.row.col.f32.f16.f16.f32 "
        "{%0,%1,%2,%3}, {%4,%5,%6,%7}, {%8,%9}, {%0,%1,%2,%3};"
        : "+f"(c[0]), "+f"(c[1]), "+f"(c[2]), "+f"(c[3])
        : "r"(a[0]), "r"(a[1]), "r"(a[2]), "r"(a[3]), "r"(b0), "r"(b1));
}
__device__ __forceinline__ void cp16(uint32_t sdst, const void* gsrc) {
    asm volatile("cp.async.cg.shared.global [%0], [%1], 16;" :: "r"(sdst), "l"(gsrc));
}
#define CP_COMMIT() asm volatile("cp.async.commit_group;" ::: "memory")
#define CP_WAIT1()  asm volatile("cp.async.wait_group 1;" ::: "memory")

__device__ __forceinline__ unsigned ld_acq(const unsigned* p) {
    unsigned v;
    asm volatile("ld.acquire.gpu.global.u32 %0, [%1];" : "=r"(v) : "l"(p) : "memory");
    return v;
}
__device__ __forceinline__ void red_release(unsigned* p, unsigned v) {
    asm volatile("red.release.gpu.global.add.u32 [%0], %1;" :: "l"(p), "r"(v) : "memory");
}

// packed f32x2 fma (sm_100+ base ISA)
__device__ __forceinline__ void fma2(unsigned long long& c, unsigned long long a, unsigned long long b) {
    asm volatile("fma.rn.f32x2 %0, %1, %2, %0;" : "+l"(c) : "l"(a), "l"(b));
}
__device__ __forceinline__ float pairsum(unsigned long long v) {
    float2 f; memcpy(&f, &v, 8); return f.x + f.y;
}
__device__ __forceinline__ float4 ldcg4(const float* p) {
    float4 v;
    asm volatile("ld.global.cg.v4.f32 {%0,%1,%2,%3}, [%4];"
        : "=f"(v.x), "=f"(v.y), "=f"(v.z), "=f"(v.w) : "l"(p));
    return v;
}

// ------------------------- fused prep kernel --------------------------------
#define PB0 32                       // prep:      [0, 32)
#define PB1 (PB0 + 30)               // pack_bias: [32, 62)
#define PB2 (PB1 + 768)              // tran:      [62, 830)
#define PB3 (PB2 + 8192)             // qkvo:      [830, 9022)
#define PB4 (PB3 + 768)              // ih conv:   [9022, 9790)
#define PB5 (PB4 + 10240)            // xconv:     [9790, 20030)
__global__ __launch_bounds__(256) void wprep(
    const int* __restrict__ mask,
    const float* __restrict__ bq, const float* __restrict__ bk, const float* __restrict__ bv,
    const float* __restrict__ bihf, const float* __restrict__ bihb,
    const float* __restrict__ W_tran,
    const float* __restrict__ Wq, const float* __restrict__ Wk,
    const float* __restrict__ Wv, const float* __restrict__ Wo,
    const float* __restrict__ Wihf, const float* __restrict__ Wihb,
    const float* __restrict__ x,
    __half* __restrict__ wh, __half* __restrict__ xh)
{
    __shared__ __align__(16) char shbuf[32*33*4];
    int b = blockIdx.x;
    int tid = threadIdx.x;

    if (b < PB0) {
        int* red = (int*)shbuf;
        red[tid] = mask[b*TT + tid];
        __syncthreads();
        for (int st = 128; st > 0; st >>= 1) {
            if (tid < st) red[tid] += red[tid + st];
            __syncthreads();
        }
        if (tid == 0) g_len[b] = red[0];
        if (b == 0 && tid < 16) g_bar[tid] = 0u;
    } else if (b < PB1) {
        int idx = (b - PB0) * 256 + tid;
        if (idx < 6144) {
            int l = idx / 3072, j = idx % 3072;
            float v;
            if (j < 1024)      v = bq[l*1024 + j];
            else if (j < 2048) v = bk[l*1024 + j - 1024];
            else               v = bv[l*1024 + j - 2048];
            g_bias[idx] = v;
        } else {
            int j = idx - 6144;
            g_bias[idx] = (j < 768) ? bihf[j] : bihb[j - 768];
        }
    } else if (b < PB3) {
        const float* W; __half* out; int K, N, bx, by;
        if (b < PB2) {
            int i2 = b - PB1;
            W = W_tran; out = wh + OFF_TRAN; K = 1536; N = 512;
            bx = i2 & 15; by = i2 >> 4;
        } else {
            int i2 = b - PB2;
            int unit = i2 >> 10, w = i2 & 1023;
            int l = unit >> 2, j = unit & 3;
            const float* src = (j == 0) ? Wq : (j == 1) ? Wk : (j == 2) ? Wv : Wo;
            W = src + (size_t)l * DD * DD;
            out = (j < 3) ? (wh + OFF_QKV(l) + (size_t)j * 1048576) : (wh + OFF_O(l));
            K = DD; N = DD;
            bx = w & 31; by = w >> 5;
        }
        float (*ts)[33] = (float(*)[33])shbuf;
        int tx = tid & 31, ty = tid >> 5;
        int n0 = bx * 32, k0 = by * 32;
#pragma unroll
        for (int i = 0; i < 4; i++)
            ts[ty + i*8][tx] = W[(size_t)(k0 + ty + i*8) * N + n0 + tx];
        __syncthreads();
#pragma unroll
        for (int i = 0; i < 4; i++) {
            int n = n0 + ty + i*8, k = k0 + tx;
            out[(size_t)n * K + k] = __float2half_rn(ts[tx][ty + i*8]);
        }
    } else if (b < PB4) {
        int i2 = b - PB3;
        const float* src = (i2 < 384) ? Wihf : Wihb;
        __half* dst = wh + OFF_IH + ((i2 < 384) ? 0 : 786432);
        int base = ((i2 < 384) ? i2 : i2 - 384) * 256 + tid;
        float4 f0 = ((const float4*)src)[base*2];
        float4 f1 = ((const float4*)src)[base*2 + 1];
        __half2 h0 = __floats2half2_rn(f0.x, f0.y);
        __half2 h1 = __floats2half2_rn(f0.z, f0.w);
        __half2 h2 = __floats2half2_rn(f1.x, f1.y);
        __half2 h3 = __floats2half2_rn(f1.z, f1.w);
        uint4 u;
        u.x = *reinterpret_cast<uint32_t*>(&h0);
        u.y = *reinterpret_cast<uint32_t*>(&h1);
        u.z = *reinterpret_cast<uint32_t*>(&h2);
        u.w = *reinterpret_cast<uint32_t*>(&h3);
        ((uint4*)dst)[base] = u;
    } else {
        int base = (b - PB4) * 256 + tid;
        float4 f0 = ((const float4*)x)[base*2];
        float4 f1 = ((const float4*)x)[base*2 + 1];
        __half2 h0 = __floats2half2_rn(f0.x, f0.y);
        __half2 h1 = __floats2half2_rn(f0.z, f0.w);
        __half2 h2 = __floats2half2_rn(f1.x, f1.y);
        __half2 h3 = __floats2half2_rn(f1.z, f1.w);
        uint4 u;
        u.x = *reinterpret_cast<uint32_t*>(&h0);
        u.y = *reinterpret_cast<uint32_t*>(&h1);
        u.z = *reinterpret_cast<uint32_t*>(&h2);
        u.w = *reinterpret_cast<uint32_t*>(&h3);
        ((uint4*)xh)[base] = u;
    }
}

// sentinel: positions the ncu profiling window
__global__ void sentinel_k() {}

// ------------------------- HMMA fp16 GEMM (R12 config) ----------------------
// C = A[M,K](fp16) * B[N,K](fp16)^T + bias (+R fp32)
// grid (N/128, M/128), 256 threads (8 warps: 4m x 2n), K % 64 == 0, K/64 >= 2.
#define TILE144 18432                 // 128 rows * 144B pitch
#define STAGE_B (2*TILE144)           // 36864
#define GEMM_SMEM (2*STAGE_B)         // 73728

template<bool RESID, bool WF, bool WH>
__global__ __launch_bounds__(256) void gemm_h(
    const __half* __restrict__ A, int lda,
    const __half* __restrict__ B,
    const float* __restrict__ bias,
    const float* __restrict__ R, int ldr,
    float* __restrict__ Cf, __half* __restrict__ Ch,
    int N, int K)
{
    extern __shared__ char smem[];
    uint32_t sb = smem_u32(smem);
    int tid = threadIdx.x;
    int lane = tid & 31;
    int wid = tid >> 5;
    int warp_m = wid & 3;
    int warp_n = wid >> 2;
    int bn = blockIdx.x * 128, bm = blockIdx.y * 128;

    float acc[2][8][4];
#pragma unroll
    for (int a = 0; a < 2; a++)
#pragma unroll
        for (int b = 0; b < 8; b++)
#pragma unroll
            for (int c = 0; c < 4; c++) acc[a][b][c] = 0.f;

#define ISSUE(k0idx, stg)                                                      \
    {                                                                          \
        int k0 = (k0idx) * 64;                                                 \
        uint32_t sa = sb + (stg) * STAGE_B;                                    \
        _Pragma("unroll")                                                      \
        for (int i = 0; i < 4; i++) {                                          \
            int linear = tid + i * 256;                                        \
            int row = linear >> 3, cc = linear & 7;                            \
            cp16(sa + row*144 + cc*16,                                         \
                 A + (size_t)(bm + row) * lda + k0 + cc*8);                    \
            cp16(sa + TILE144 + row*144 + cc*16,                               \
                 B + (size_t)(bn + row) * K + k0 + cc*8);                      \
        }                                                                      \
    }

    const int NC = K / 64;
    ISSUE(0, 0); CP_COMMIT();
    ISSUE(1, 1); CP_COMMIT();

    for (int ch = 0; ch < NC; ch++) {
        CP_WAIT1();
        __syncthreads();

        uint32_t sbase = sb + (ch & 1) * STAGE_B;
#pragma unroll
        for (int ks = 0; ks < 4; ks++) {
            int kofs = ks * 32;   // bytes (16 halfs)
            uint32_t ah[2][4];
#pragma unroll
            for (int mf = 0; mf < 2; mf++) {
                uint32_t row = warp_m * 32 + mf * 16 + (lane & 15);
                uint32_t addr = sbase + row * 144 + kofs + ((lane >> 4) * 16);
                ldsm4(ah[mf], addr);
            }
#pragma unroll
            for (int np = 0; np < 4; np++) {
                uint32_t rown = warp_n * 64 + np * 16 + (lane & 7) + ((lane >> 4) << 3);
                uint32_t addr = sbase + TILE144 + rown * 144 + kofs + (((lane >> 3) & 1) * 16);
                uint32_t b[4];
                ldsm4(b, addr);
#pragma unroll
                for (int mf = 0; mf < 2; mf++) {
                    mma_fp16(acc[mf][np*2],   ah[mf], b[0], b[1]);
                    mma_fp16(acc[mf][np*2+1], ah[mf], b[2], b[3]);
                }
            }
        }

        __syncthreads();
        int nxt = ch + 2;
        if (nxt < NC) ISSUE(nxt, nxt & 1);
        CP_COMMIT();
    }

    // ---- epilogue ----
#pragma unroll
    for (int mf = 0; mf < 2; mf++) {
        int row0 = bm + warp_m * 32 + mf * 16 + (lane >> 2);
        int row1 = row0 + 8;
#pragma unroll
        for (int nf = 0; nf < 8; nf++) {
            int col = bn + warp_n * 64 + nf * 8 + (lane & 3) * 2;
            float2 bs = *(const float2*)(bias + col);
            float* a4 = acc[mf][nf];
            float2 o0 = make_float2(a4[0] + bs.x, a4[1] + bs.y);
            float2 o1 = make_float2(a4[2] + bs.x, a4[3] + bs.y);
            if (RESID) {
                float2 r0 = *(const float2*)(R + (size_t)row0 * ldr + col);
                float2 r1 = *(const float2*)(R + (size_t)row1 * ldr + col);
                o0.x += r0.x; o0.y += r0.y;
                o1.x += r1.x; o1.y += r1.y;
            }
            if (WF) {
                *(float2*)(Cf + (size_t)row0 * N + col) = o0;
                *(float2*)(Cf + (size_t)row1 * N + col) = o1;
            }
            if (WH) {
                *(__half2*)(Ch + (size_t)row0 * N + col) = __floats2half2_rn(o0.x, o0.y);
                *(__half2*)(Ch + (size_t)row1 * N + col) = __floats2half2_rn(o1.x, o1.y);
            }
        }
    }
#undef ISSUE
}

// ------------------------- banded attention (fp16 in/out) -------------------
__global__ __launch_bounds__(256) void band_attn(
    const __half* __restrict__ qkv, __half* __restrict__ o)
{
    int t = blockIdx.x, b = blockIdx.y;
    int hh = threadIdx.x >> 5;
    int lane = threadIdx.x & 31;
    const float scale = 0.088388347648318447f;

    size_t qb = ((size_t)(b*TT + t))*3072 + hh*DH + lane*4;
    float2 q01, q23;
    {
        const __half2* qp = (const __half2*)(qkv + qb);
        q01 = __half22float2(qp[0]);
        q23 = __half22float2(qp[1]);
    }

    float s[7];
    float m = -1e30f;
#pragma unroll
    for (int jj = 0; jj < 7; jj++) {
        int j = t - 3 + jj;
        bool ok = (j >= 0) && (j < TT);
        int jc = j < 0 ? 0 : (j > TT-1 ? TT-1 : j);
        size_t kb = ((size_t)(b*TT + jc))*3072 + 1024 + hh*DH + lane*4;
        const __half2* kp = (const __half2*)(qkv + kb);
        float2 k01 = __half22float2(kp[0]);
        float2 k23 = __half22float2(kp[1]);
        float d = q01.x*k01.x + q01.y*k01.y + q23.x*k23.x + q23.y*k23.y;
        d += __shfl_xor_sync(0xffffffffu, d, 16);
        d += __shfl_xor_sync(0xffffffffu, d, 8);
        d += __shfl_xor_sync(0xffffffffu, d, 4);
        d += __shfl_xor_sync(0xffffffffu, d, 2);
        d += __shfl_xor_sync(0xffffffffu, d, 1);
        d *= scale;
        s[jj] = ok ? d : -1e30f;
        m = fmaxf(m, s[jj]);
    }
    float sum = 0.f;
#pragma unroll
    for (int jj = 0; jj < 7; jj++) { s[jj] = expf(s[jj] - m); sum += s[jj]; }
    float inv = 1.f / sum;

    float4 acc = make_float4(0.f, 0.f, 0.f, 0.f);
#pragma unroll
    for (int jj = 0; jj < 7; jj++) {
        int j = t - 3 + jj;
        int jc = j < 0 ? 0 : (j > TT-1 ? TT-1 : j);
        size_t vb = ((size_t)(b*TT + jc))*3072 + 2048 + hh*DH + lane*4;
        const __half2* vp = (const __half2*)(qkv + vb);
        float2 v01 = __half22float2(vp[0]);
        float2 v23 = __half22float2(vp[1]);
        float p = s[jj] * inv;
        acc.x += p*v01.x; acc.y += p*v01.y; acc.z += p*v23.x; acc.w += p*v23.y;
    }
    size_t ob = ((size_t)(b*TT + t))*DD + hh*DH + lane*4;
    *(__half2*)(o + ob)     = __floats2half2_rn(acc.x, acc.y);
    *(__half2*)(o + ob + 2) = __floats2half2_rn(acc.z, acc.w);
}

// ------------------------- persistent bidirectional GRU (k-split) -----------
// 128 CTAs: dir(2) x unit-group(8, 32 units) x batch-group(8, 4 batches)
// 256 threads: (u 0..31, bl 0..3, kh 0..1). Lane pair (kh 0/1) splits the
// K=256 dot in half; combined by shfl_xor(1). 2 warps/SMSP hide latency.
// smem gap layout: k>=128 stored at +4 words so the kh split is conflict-free.
#define WPITCH 264
#define GRU_SMEM ((96*WPITCH + 4*WPITCH) * 4)   // 105,600 B

__global__ __launch_bounds__(256) void gru_kernel(
    const float* __restrict__ gx,
    const float* __restrict__ Whf, const float* __restrict__ Whb,
    const float* __restrict__ bhf, const float* __restrict__ bhb,
    float* __restrict__ out)
{
    extern __shared__ float sm[];
    float* ws = sm;                   // [96][264] (gap at k=128)
    float* hs = sm + 96*WPITCH;       // [4][264]  (gap at k=128)

    int cta = blockIdx.x;
    int dir = cta >> 6;
    int ug  = (cta >> 3) & 7;
    int bg  = cta & 7;
    int grp = (dir << 3) | bg;
    int tid = threadIdx.x;
    int u   = tid >> 3;          // 0..31
    int bl  = (tid >> 1) & 3;    // 0..3
    int kh  = tid & 1;           // 0..1
    int unit  = ug*32 + u;
    int batch = bg*4 + bl;

    const float* Wh = dir ? Whb : Whf;
    const float* bh = dir ? bhb : bhf;

    // weight load with gap layout: row = g*32+uu
    for (int idx = tid; idx < 96*256; idx += 256) {
        int row = idx >> 8;
        int kk  = idx & 255;
        ws[row*WPITCH + (kk < 128 ? kk : kk + 4)] =
            Wh[((size_t)((row >> 5) << 8) + ug*32 + (row & 31))*256 + kk];
    }
    float br  = bh[unit];
    float bz  = bh[256 + unit];
    float bnn = bh[512 + unit];
    int len = g_len[batch];

    if (kh == 0)
        __stcg(&g_hstate[((dir*2 + 0)*BB + batch)*HID + unit], 0.f);
    __syncthreads();
    if (tid == 0) red_release(&g_bar[grp], 1u);

    const float* wr = &ws[(0*32 + u)*WPITCH + kh*132];
    const float* wz = &ws[(1*32 + u)*WPITCH + kh*132];
    const float* wn = &ws[(2*32 + u)*WPITCH + kh*132];
    int hpidx = bl*WPITCH + (unit < 128 ? unit : unit + 4);

    unsigned target = 8u;
    for (int s = 0; s < TT; s++, target += 8u) {
        // gx AND out prefetch: h-independent, issue before the spin
        int tt;
        if (dir == 0) tt = s;
        else { int ti = len - 1 - s; tt = ti < 0 ? 0 : ti; }
        const float* gxp = gx + ((size_t)batch*TT + tt)*1536 + dir*768;
        float gr = gxp[unit];
        float gz = gxp[256 + unit];
        float gn = gxp[512 + unit];

        float* op = nullptr;
        float oprev = 0.f;
        if (kh == 0 && s < len) {
            int tout = (dir == 0) ? s : (len - 1 - s);
            op = out + ((size_t)batch*TT + tout)*512 + dir*256 + unit;
            oprev = *op;                  // prefetch old value (x_face contrib)
        }

        // all threads poll (acquire)
        while (ld_acq(&g_bar[grp]) < target) {}

        // stage h: one float4 per thread, gap layout
        {
            int b2 = tid >> 6;
            int k2 = (tid * 4) & 255;
            float4 v = ldcg4(&g_hstate[((size_t)(dir*2 + (s & 1))*BB + bg*4 + b2)*HID + k2]);
            *(float4*)&hs[b2*WPITCH + (k2 < 128 ? k2 : k2 + 4)] = v;
        }
        __syncthreads();

        const float* hb = &hs[bl*WPITCH + kh*132];
        unsigned long long ar0=0, ar1=0, az0=0, az1=0, an0=0, an1=0;
#pragma unroll 8
        for (int kk = 0; kk < 128; kk += 4) {
            ulonglong2 hv = *(const ulonglong2*)(hb + kk);
            ulonglong2 w1 = *(const ulonglong2*)(wr + kk);
            ulonglong2 w2 = *(const ulonglong2*)(wz + kk);
            ulonglong2 w3 = *(const ulonglong2*)(wn + kk);
            fma2(ar0, hv.x, w1.x); fma2(ar1, hv.y, w1.y);
            fma2(az0, hv.x, w2.x); fma2(az1, hv.y, w2.y);
            fma2(an0, hv.x, w3.x); fma2(an1, hv.y, w3.y);
        }
        float ghr = pairsum(ar0) + pairsum(ar1);
        float ghz = pairsum(az0) + pairsum(az1);
        float ghn = pairsum(an0) + pairsum(an1);
        ghr += __shfl_xor_sync(0xffffffffu, ghr, 1);
        ghz += __shfl_xor_sync(0xffffffffu, ghz, 1);
        ghn += __shfl_xor_sync(0xffffffffu, ghn, 1);

        float hn = 0.f;
        if (kh == 0) {
            float r = 1.f / (1.f + expf(-(gr + ghr + br)));
            float z = 1.f / (1.f + expf(-(gz + ghz + bz)));
            float n = tanhf(gn + r*(ghn + bnn));
            float hp = hs[hpidx];
            hn = (1.f - z)*n + z*hp;
            __stcg(&g_hstate[((size_t)(dir*2 + ((s+1) & 1))*BB + batch)*HID + unit], hn);
        }
        __syncthreads();
        if (tid == 0) red_release(&g_bar[grp], 1u);

        if (op) *op = oprev + hn;
    }
}

// ------------------------- launch ------------------------------------------
extern "C" void kernel_launch(void* const* d_in, const int* in_sizes, int n_in,
                              void* d_out, int out_size)
{
    const float* x      = (const float*)d_in[0];
    const int*   mask   = (const int*)  d_in[1];
    const float* W_tran = (const float*)d_in[2];
    const float* b_tran = (const float*)d_in[3];
    const float* Wq     = (const float*)d_in[4];
    const float* bq     = (const float*)d_in[5];
    const float* Wk     = (const float*)d_in[6];
    const float* bk     = (const float*)d_in[7];
    const float* Wv     = (const float*)d_in[8];
    const float* bv     = (const float*)d_in[9];
    const float* Wo     = (const float*)d_in[10];
    const float* bo     = (const float*)d_in[11];
    const float* Wihf   = (const float*)d_in[12];
    const float* Whhf   = (const float*)d_in[13];
    const float* bihf   = (const float*)d_in[14];
    const float* bhhf   = (const float*)d_in[15];
    const float* Wihb   = (const float*)d_in[16];
    const float* Whhb   = (const float*)d_in[17];
    const float* bihb   = (const float*)d_in[18];
    const float* bhhb   = (const float*)d_in[19];
    float* out = (float*)d_out;

    float *hbuf, *gxb, *biasbuf;
    __half *wh, *xh, *hh, *qkvh, *aoh;
    cudaGetSymbolAddress((void**)&hbuf,  g_h);
    cudaGetSymbolAddress((void**)&hh,    g_hh);
    cudaGetSymbolAddress((void**)&xh,    g_xh);
    cudaGetSymbolAddress((void**)&qkvh,  g_qkv);
    cudaGetSymbolAddress((void**)&aoh,   g_ao);
    cudaGetSymbolAddress((void**)&gxb,   g_gx);
    cudaGetSymbolAddress((void**)&wh,    g_Wh);
    cudaGetSymbolAddress((void**)&biasbuf, g_bias);

    cudaFuncSetAttribute(gru_kernel, cudaFuncAttributeMaxDynamicSharedMemorySize, 112*1024);
    cudaFuncSetAttribute(gemm_h<false,true,false>,  cudaFuncAttributeMaxDynamicSharedMemorySize, GEMM_SMEM);
    cudaFuncSetAttribute(gemm_h<false,false,true>,  cudaFuncAttributeMaxDynamicSharedMemorySize, GEMM_SMEM);
    cudaFuncSetAttribute(gemm_h<true,true,true>,    cudaFuncAttributeMaxDynamicSharedMemorySize, GEMM_SMEM);

    // one fused prep launch
    wprep<<<PB5, 256>>>(mask, bq, bk, bv, bihf, bihb,
                        W_tran, Wq, Wk, Wv, Wo, Wihf, Wihb, x, wh, xh);

    // x_face -> out (fp32)
    gemm_h<false,true,false><<<dim3(4, 64), 256, GEMM_SMEM>>>(
        xh + 1024, XF, wh + OFF_TRAN, b_tran, nullptr, 0, out, nullptr, 512, 1536);

    // sentinel: aligns the ncu window onto a QKV GEMM
    sentinel_k<<<1, 32>>>();

    for (int l = 0; l < 2; l++) {
        const __half* Ain = (l == 0) ? xh : hh;
        int lda = (l == 0) ? XF : DD;

        // fused QKV: N = 3072, fp16 out
        gemm_h<false,false,true><<<dim3(24, 64), 256, GEMM_SMEM>>>(
            Ain, lda, wh + OFF_QKV(l), biasbuf + l*3072, nullptr, 0,
            nullptr, qkvh, 3072, DD);

        band_attn<<<dim3(TT, BB), 256>>>(qkvh, aoh);

        // O proj + residual: fp32 h and fp16 hh outputs
        const float* Rres = (l == 0) ? x : hbuf;
        int ldr = (l == 0) ? XF : DD;
        gemm_h<true,true,true><<<dim3(8, 64), 256, GEMM_SMEM>>>(
            aoh, DD, wh + OFF_O(l), bo + (size_t)l*DD, Rres, ldr,
            hbuf, hh, DD, DD);
    }

    // fused GRU input projections: N = 1536 (f | b), fp32 out
    gemm_h<false,true,false><<<dim3(12, 64), 256, GEMM_SMEM>>>(
        hh, DD, wh + OFF_IH, biasbuf + 6144, nullptr, 0, gxb, nullptr, 1536, DD);

    // persistent bidirectional GRU (k-split, 256 threads), out = x_face + ys
    gru_kernel<<<128, 256, GRU_SMEM>>>(gxb, Whhf, Whhb, bhhf, bhhb, out);
}